// round 2
// baseline (speedup 1.0000x reference)
#include <cuda_runtime.h>
#include <cuda_bf16.h>
#include <math.h>

// Problem constants
#define Bq 4
#define Sq 2048
#define Eq 1024

// Scratch (allocation-free rule: __device__ globals)
__device__ float g_q[Bq * Sq * Eq];
__device__ float g_k[Bq * Sq * Eq];
__device__ float g_v[Bq * Sq * Eq];
__device__ float g_s[(size_t)Bq * Sq * Sq];

#define BM 128
#define BN 128
#define BK 8
#define TM 8
#define TN 8
#define NTHREADS 256

// C[M,N] = A[M,K] @ B  where B is [K,N] (TRANS_B=0) or [N,K] (TRANS_B=1, i.e. A@B^T).
// All of M,N divisible by 128, K divisible by 8. Batched via blockIdx.z with strides.
template <int TRANS_B>
__global__ __launch_bounds__(NTHREADS)
void sgemm_kernel(const float* __restrict__ A, const float* __restrict__ B,
                  float* __restrict__ C, int M, int N, int K,
                  long strideA, long strideB, long strideC) {
    __shared__ float As[BK][BM];
    __shared__ float Bs[BK][BN];

    A += (long)blockIdx.z * strideA;
    B += (long)blockIdx.z * strideB;
    C += (long)blockIdx.z * strideC;

    const int tid = threadIdx.x;
    const int m0 = blockIdx.y * BM;
    const int n0 = blockIdx.x * BN;

    // A tile: 128 rows x 8 cols -> one float4 per thread
    const int arow = tid >> 1;          // 0..127
    const int acol = (tid & 1) * 4;     // 0 or 4
    // B tile (NN): 8 rows x 128 cols -> one float4 per thread
    const int brow = tid >> 5;          // 0..7
    const int bcol = (tid & 31) * 4;    // 0..124

    const int trow = (tid >> 4) * TM;   // 0..120
    const int tcol = (tid & 15) * TN;   // 0..120

    float acc[TM][TN];
#pragma unroll
    for (int i = 0; i < TM; i++)
#pragma unroll
        for (int j = 0; j < TN; j++) acc[i][j] = 0.0f;

    for (int k0 = 0; k0 < K; k0 += BK) {
        // load A tile (transpose into As[k][m])
        float4 a = *(const float4*)&A[(long)(m0 + arow) * K + k0 + acol];
        As[acol + 0][arow] = a.x;
        As[acol + 1][arow] = a.y;
        As[acol + 2][arow] = a.z;
        As[acol + 3][arow] = a.w;

        if (TRANS_B) {
            // B is [N,K]: tile 128 n-rows x 8 k-cols, transpose into Bs[k][n]
            float4 b = *(const float4*)&B[(long)(n0 + arow) * K + k0 + acol];
            Bs[acol + 0][arow] = b.x;
            Bs[acol + 1][arow] = b.y;
            Bs[acol + 2][arow] = b.z;
            Bs[acol + 3][arow] = b.w;
        } else {
            // B is [K,N]: tile 8 k-rows x 128 n-cols, direct
            float4 b = *(const float4*)&B[(long)(k0 + brow) * N + n0 + bcol];
            *(float4*)&Bs[brow][bcol] = b;
        }
        __syncthreads();

#pragma unroll
        for (int kk = 0; kk < BK; kk++) {
            float ra[TM], rb[TN];
#pragma unroll
            for (int i = 0; i < TM; i++) ra[i] = As[kk][trow + i];
#pragma unroll
            for (int j = 0; j < TN; j++) rb[j] = Bs[kk][tcol + j];
#pragma unroll
            for (int i = 0; i < TM; i++)
#pragma unroll
                for (int j = 0; j < TN; j++) acc[i][j] = fmaf(ra[i], rb[j], acc[i][j]);
        }
        __syncthreads();
    }

#pragma unroll
    for (int i = 0; i < TM; i++) {
#pragma unroll
        for (int j = 0; j < TN; j += 4) {
            float4 o;
            o.x = acc[i][j + 0];
            o.y = acc[i][j + 1];
            o.z = acc[i][j + 2];
            o.w = acc[i][j + 3];
            *(float4*)&C[(long)(m0 + trow + i) * N + n0 + tcol + j] = o;
        }
    }
}

// Row softmax over rows of length 2048, followed by division by 32 (= sqrt(E)).
// One CTA (256 threads) per row; 8 elements per thread, kept in registers.
__global__ __launch_bounds__(256)
void softmax_scale_kernel(float* __restrict__ S) {
    const int n = Sq;                      // 2048
    float* row = S + (long)blockIdx.x * n;
    const int tid = threadIdx.x;

    float vals[8];
    float m = -INFINITY;
#pragma unroll
    for (int i = 0; i < 8; i++) {
        vals[i] = row[tid + i * 256];
        m = fmaxf(m, vals[i]);
    }

    __shared__ float red[256];
    red[tid] = m;
    __syncthreads();
    for (int s = 128; s > 0; s >>= 1) {
        if (tid < s) red[tid] = fmaxf(red[tid], red[tid + s]);
        __syncthreads();
    }
    m = red[0];
    __syncthreads();

    float sum = 0.0f;
#pragma unroll
    for (int i = 0; i < 8; i++) {
        vals[i] = expf(vals[i] - m);
        sum += vals[i];
    }
    red[tid] = sum;
    __syncthreads();
    for (int s = 128; s > 0; s >>= 1) {
        if (tid < s) red[tid] += red[tid + s];
        __syncthreads();
    }
    const float inv = 1.0f / (red[0] * 32.0f);   // SCALE = sqrt(1024) = 32
#pragma unroll
    for (int i = 0; i < 8; i++) row[tid + i * 256] = vals[i] * inv;
}

extern "C" void kernel_launch(void* const* d_in, const int* in_sizes, int n_in,
                              void* d_out, int out_size) {
    const float* values  = (const float*)d_in[0];
    const float* keys    = (const float*)d_in[1];
    const float* queries = (const float*)d_in[2];
    const float* Wv      = (const float*)d_in[3];
    const float* Wk      = (const float*)d_in[4];
    const float* Wq      = (const float*)d_in[5];
    float* out = (float*)d_out;

    float *q_ptr, *k_ptr, *v_ptr, *s_ptr;
    cudaGetSymbolAddress((void**)&q_ptr, g_q);
    cudaGetSymbolAddress((void**)&k_ptr, g_k);
    cudaGetSymbolAddress((void**)&v_ptr, g_v);
    cudaGetSymbolAddress((void**)&s_ptr, g_s);

    // 1) Projections: [8192,1024] = [8192,1024] @ [1024,1024]  (NN)
    {
        dim3 grid(Eq / BN, (Bq * Sq) / BM, 1);
        sgemm_kernel<0><<<grid, NTHREADS>>>(queries, Wq, q_ptr, Bq * Sq, Eq, Eq, 0, 0, 0);
        sgemm_kernel<0><<<grid, NTHREADS>>>(keys,    Wk, k_ptr, Bq * Sq, Eq, Eq, 0, 0, 0);
        sgemm_kernel<0><<<grid, NTHREADS>>>(values,  Wv, v_ptr, Bq * Sq, Eq, Eq, 0, 0, 0);
    }

    // 2) Scores: per batch, [2048,2048] = Q[2048,1024] @ K[2048,1024]^T  (NT)
    {
        dim3 grid(Sq / BN, Sq / BM, Bq);
        sgemm_kernel<1><<<grid, NTHREADS>>>(q_ptr, k_ptr, s_ptr, Sq, Sq, Eq,
                                            (long)Sq * Eq, (long)Sq * Eq, (long)Sq * Sq);
    }

    // 3) Softmax (+ divide by sqrt(E)) over each of the B*S rows
    softmax_scale_kernel<<<Bq * Sq, 256>>>(s_ptr);

    // 4) Output: per batch, [2048,1024] = P[2048,2048] @ V[2048,1024]  (NN)
    {
        dim3 grid(Eq / BN, Sq / BM, Bq);
        sgemm_kernel<0><<<grid, NTHREADS>>>(s_ptr, v_ptr, out, Sq, Eq, Sq,
                                            (long)Sq * Sq, (long)Sq * Eq, (long)Sq * Eq);
    }
    (void)in_sizes; (void)n_in; (void)out_size;
}

// round 4
// speedup vs baseline: 2.0456x; 2.0456x over previous
#include <cuda_runtime.h>
#include <cuda_bf16.h>
#include <math.h>
#include <stdint.h>

#define Bq 4
#define Sq 2048
#define Eq 1024

#define STAGES 4
#define ROWB 144                      // padded smem row bytes (64 bf16 = 128B data + 16B pad)
#define STAGE_B (256 * ROWB)          // 128 A rows + 128 B rows
#define SMEM_T (STAGES * STAGE_B)     // 147456

// ---------------- scratch ----------------
__device__ __align__(256) __nv_bfloat16 g_big[48LL << 20];   // 96MB: input A-aug, then P A-aug
__device__ __align__(256) __nv_bfloat16 g_wb[3LL << 20];     // 6MB: W B-aug
__device__ __align__(256) __nv_bfloat16 g_qa[24LL << 20];    // q A-aug [8192,3072]
__device__ __align__(256) __nv_bfloat16 g_ka[24LL << 20];    // k B-aug [4][2048,3072]
__device__ __align__(256) __nv_bfloat16 g_va[24LL << 20];    // v^T B-aug [4][1024,6144]
__device__ float g_f32[(size_t)Bq * Sq * Eq];                // fp32 temp
__device__ float g_s[(size_t)Bq * Sq * Sq];                  // fp32 logits

// ---------------- helpers ----------------
__device__ __forceinline__ uint32_t smem_u32(const void* p) {
    uint32_t a;
    asm("{ .reg .u64 t; cvta.to.shared.u64 t, %1; cvt.u32.u64 %0, t; }" : "=r"(a) : "l"(p));
    return a;
}
__device__ __forceinline__ void cpasync16(uint32_t dst, const void* src) {
    asm volatile("cp.async.cg.shared.global [%0], [%1], 16;" :: "r"(dst), "l"(src));
}
__device__ __forceinline__ void split2(float v, __nv_bfloat16& h, __nv_bfloat16& l) {
    h = __float2bfloat16(v);
    l = __float2bfloat16(v - __bfloat162float(h));
}
__device__ __forceinline__ void mma16816(float* d, const uint32_t* a, const uint32_t* b) {
    asm volatile(
        "mma.sync.aligned.m16n8k16.row.col.f32.bf16.bf16.f32 "
        "{%0,%1,%2,%3}, {%4,%5,%6,%7}, {%8,%9}, {%0,%1,%2,%3};"
        : "+f"(d[0]), "+f"(d[1]), "+f"(d[2]), "+f"(d[3])
        : "r"(a[0]), "r"(a[1]), "r"(a[2]), "r"(a[3]), "r"(b[0]), "r"(b[1]));
}

// ---------------- split fp32 -> augmented bf16 (row-major [R, 3K]) ----------------
// A-pattern slots {k,K+k,2K+k} = {hi,hi,lo}; B-pattern = {hi,lo,hi}. TRANS: dst[r][k]=src[k][r].
template <bool APAT, bool TRANS>
__global__ __launch_bounds__(256) void split_aug(const float* __restrict__ src,
                                                 __nv_bfloat16* __restrict__ dst,
                                                 int Rout, int K, long long sZ, long long dZ) {
    src += blockIdx.y * sZ;
    dst += blockIdx.y * dZ;
    long long idx = (long long)blockIdx.x * 256 + threadIdx.x;
    int row, kp;
    float v0, v1;
    if (TRANS) {
        row = (int)(idx % Rout);
        kp = (int)(idx / Rout) * 2;
        v0 = src[(long long)kp * Rout + row];
        v1 = src[(long long)(kp + 1) * Rout + row];
    } else {
        const int hk = K >> 1;
        row = (int)(idx / hk);
        kp = (int)(idx % hk) * 2;
        v0 = src[(long long)row * K + kp];
        v1 = src[(long long)row * K + kp + 1];
    }
    __nv_bfloat16 h0, l0, h1, l1;
    split2(v0, h0, l0);
    split2(v1, h1, l1);
    __nv_bfloat162 H, L;
    H.x = h0; H.y = h1;
    L.x = l0; L.y = l1;
    __nv_bfloat162* d = (__nv_bfloat162*)(dst + (long long)row * 3 * K);
    d[kp >> 1] = H;
    d[(K + kp) >> 1] = APAT ? H : L;
    d[(2 * K + kp) >> 1] = APAT ? L : H;
}

// ---------------- pipelined bf16 mma.sync GEMM ----------------
// C[128,128 per CTA] fp32 = A[M,Kp] @ B[N,Kp]^T, both K-major bf16. Kp % 64 == 0.
__global__ __launch_bounds__(256, 1)
void gemm_bf16(const __nv_bfloat16* __restrict__ A, const __nv_bfloat16* __restrict__ B,
               float* __restrict__ C, int N, int Kp,
               long long aZ, long long bZ, long long cZ) {
    extern __shared__ char smem[];
    const uint32_t sb = smem_u32(smem);
    const int tid = threadIdx.x;
    const int lane = tid & 31, g = lane >> 2, c = lane & 3;
    const int wid = tid >> 5, wm = wid & 1, wn = wid >> 1;
    const int KT = Kp >> 6;

    const char* Ab = (const char*)(A + blockIdx.z * aZ + (long long)(blockIdx.y * 128) * Kp);
    const char* Bb = (const char*)(B + blockIdx.z * bZ + (long long)(blockIdx.x * 128) * Kp);
    const long long rowbytes = (long long)Kp * 2;

    int lr[4], ls[4];
#pragma unroll
    for (int t = 0; t < 4; t++) {
        int idx = tid + 256 * t;
        lr[t] = idx >> 3;
        ls[t] = (idx & 7) * 16;
    }

#define LOADSTAGE(s, ck)                                                                   \
    {                                                                                      \
        uint32_t b0_ = sb + (s) * STAGE_B;                                                 \
        long long off_ = (long long)(ck) * 128;                                            \
        _Pragma("unroll") for (int t = 0; t < 4; t++) {                                    \
            cpasync16(b0_ + lr[t] * ROWB + ls[t], Ab + lr[t] * rowbytes + off_ + ls[t]);   \
            cpasync16(b0_ + (128 + lr[t]) * ROWB + ls[t],                                  \
                      Bb + lr[t] * rowbytes + off_ + ls[t]);                               \
        }                                                                                  \
        asm volatile("cp.async.commit_group;");                                            \
    }

    float acc[4][4][4];
#pragma unroll
    for (int i = 0; i < 4; i++)
#pragma unroll
        for (int j = 0; j < 4; j++)
#pragma unroll
            for (int r = 0; r < 4; r++) acc[i][j][r] = 0.0f;

    LOADSTAGE(0, 0)
    LOADSTAGE(1, 1)
    LOADSTAGE(2, 2)

    for (int k = 0; k < KT; k++) {
        asm volatile("cp.async.wait_group 2;");
        __syncthreads();
        const uint32_t* S = (const uint32_t*)(smem + (k & 3) * STAGE_B);   // row stride 36 u32
#pragma unroll
        for (int ks = 0; ks < 4; ks++) {
            uint32_t af[4][4], bfr[4][2];
#pragma unroll
            for (int i = 0; i < 4; i++) {
                const int r0 = wm * 64 + i * 16 + g;
                const int o = r0 * 36 + ks * 8 + c;
                af[i][0] = S[o];
                af[i][1] = S[o + 8 * 36];
                af[i][2] = S[o + 4];
                af[i][3] = S[o + 8 * 36 + 4];
            }
#pragma unroll
            for (int j = 0; j < 4; j++) {
                const int rb = 128 + wn * 32 + j * 8 + g;
                const int o = rb * 36 + ks * 8 + c;
                bfr[j][0] = S[o];
                bfr[j][1] = S[o + 4];
            }
#pragma unroll
            for (int i = 0; i < 4; i++)
#pragma unroll
                for (int j = 0; j < 4; j++) mma16816(acc[i][j], af[i], bfr[j]);
        }
        __syncthreads();
        if (k + 3 < KT) LOADSTAGE((k + 3) & 3, k + 3)
    }

    float* Cb = C + blockIdx.z * cZ;
#pragma unroll
    for (int i = 0; i < 4; i++) {
#pragma unroll
        for (int j = 0; j < 4; j++) {
            const int r0 = blockIdx.y * 128 + wm * 64 + i * 16 + g;
            const int col = blockIdx.x * 128 + wn * 32 + j * 8 + 2 * c;
            float2 lo, hi;
            lo.x = acc[i][j][0]; lo.y = acc[i][j][1];
            hi.x = acc[i][j][2]; hi.y = acc[i][j][3];
            *(float2*)&Cb[(long long)r0 * N + col] = lo;
            *(float2*)&Cb[(long long)(r0 + 8) * N + col] = hi;
        }
    }
#undef LOADSTAGE
}

// ---------------- softmax (in place) + /32 ----------------
__global__ __launch_bounds__(256) void softmax_k(float* __restrict__ S) {
    float* row = S + (long long)blockIdx.x * Sq;
    const int tid = threadIdx.x;
    float vals[8], m = -INFINITY;
#pragma unroll
    for (int i = 0; i < 8; i++) { vals[i] = row[tid + i * 256]; m = fmaxf(m, vals[i]); }
    __shared__ float red[256];
    red[tid] = m;
    __syncthreads();
    for (int s = 128; s > 0; s >>= 1) { if (tid < s) red[tid] = fmaxf(red[tid], red[tid + s]); __syncthreads(); }
    m = red[0];
    __syncthreads();
    float sum = 0.f;
#pragma unroll
    for (int i = 0; i < 8; i++) { vals[i] = expf(vals[i] - m); sum += vals[i]; }
    red[tid] = sum;
    __syncthreads();
    for (int s = 128; s > 0; s >>= 1) { if (tid < s) red[tid] += red[tid + s]; __syncthreads(); }
    const float inv = 1.0f / (red[0] * 32.0f);
#pragma unroll
    for (int i = 0; i < 8; i++) row[tid + i * 256] = vals[i] * inv;
}

extern "C" void kernel_launch(void* const* d_in, const int* in_sizes, int n_in,
                              void* d_out, int out_size) {
    const float* values  = (const float*)d_in[0];
    const float* keys    = (const float*)d_in[1];
    const float* queries = (const float*)d_in[2];
    const float* Wv = (const float*)d_in[3];
    const float* Wk = (const float*)d_in[4];
    const float* Wq = (const float*)d_in[5];
    float* out = (float*)d_out;

    __nv_bfloat16 *big, *wb, *qa, *ka, *va;
    float *f32, *sc;
    cudaGetSymbolAddress((void**)&big, g_big);
    cudaGetSymbolAddress((void**)&wb, g_wb);
    cudaGetSymbolAddress((void**)&qa, g_qa);
    cudaGetSymbolAddress((void**)&ka, g_ka);
    cudaGetSymbolAddress((void**)&va, g_va);
    cudaGetSymbolAddress((void**)&f32, g_f32);
    cudaGetSymbolAddress((void**)&sc, g_s);

    cudaFuncSetAttribute(gemm_bf16, cudaFuncAttributeMaxDynamicSharedMemorySize, SMEM_T);

    const struct { const float* X; const float* W; } P3[3] = {{queries, Wq}, {keys, Wk}, {values, Wv}};

    for (int p = 0; p < 3; p++) {
        // input [8192,1024] -> A-aug [8192,3072]; W [1024(e),1024(f)] -> B-aug [1024(f),3072] (trans)
        split_aug<true, false><<<dim3(16384, 1), 256>>>(P3[p].X, big, 8192, 1024, 0, 0);
        split_aug<false, true><<<dim3(2048, 1), 256>>>(P3[p].W, wb, 1024, 1024, 0, 0);
        gemm_bf16<<<dim3(8, 64, 1), 256, SMEM_T>>>(big, wb, f32, 1024, 3072, 0, 0, 0);
        if (p == 0)       // q -> A-aug (flat M=8192)
            split_aug<true, false><<<dim3(16384, 1), 256>>>(f32, qa, 8192, 1024, 0, 0);
        else if (p == 1)  // k -> B-aug per batch [2048,3072]
            split_aug<false, false><<<dim3(4096, 4), 256>>>(f32, ka, 2048, 1024,
                                                            (long long)Sq * Eq, 2048LL * 3072);
        else              // v^T -> B-aug per batch [1024,6144]
            split_aug<false, true><<<dim3(4096, 4), 256>>>(f32, va, 1024, 2048,
                                                           (long long)Sq * Eq, 1024LL * 6144);
    }

    // scores = q @ k^T per batch
    gemm_bf16<<<dim3(16, 16, 4), 256, SMEM_T>>>(qa, ka, sc, 2048, 3072,
                                                2048LL * 3072, 2048LL * 3072, (long long)Sq * Sq);
    // softmax + /32
    softmax_k<<<Bq * Sq, 256>>>(sc);
    // P -> A-aug per batch [2048,6144]
    split_aug<true, false><<<dim3(8192, 4), 256>>>(sc, big, 2048, 2048,
                                                   (long long)Sq * Sq, 2048LL * 6144);
    // out = P @ v per batch
    gemm_bf16<<<dim3(8, 16, 4), 256, SMEM_T>>>(big, va, out, 1024, 6144,
                                               2048LL * 6144, 1024LL * 6144, (long long)Sq * Eq);

    (void)in_sizes; (void)n_in; (void)out_size;
}

// round 6
// speedup vs baseline: 2.2911x; 1.1200x over previous
#include <cuda_runtime.h>
#include <cuda_bf16.h>
#include <math.h>
#include <stdint.h>

#define Bq 4
#define Sq 2048
#define Eq 1024

#define STAGES 4
#define ROWB 144                       // 64 bf16 = 128B data + 16B pad
#define STAGE_B (384 * ROWB)           // 128 A rows + 256 B rows = 55296 B
#define SMEM_T (STAGES * STAGE_B)      // 221184 B

// ---------------- scratch ----------------
__device__ __align__(256) __nv_bfloat16 g_big[48LL << 20];   // input A-aug (48MB) then P-aug (96MB)
__device__ __align__(256) __nv_bfloat16 g_wb[3LL << 20];     // W B-aug
__device__ __align__(256) __nv_bfloat16 g_qa[24LL << 20];    // q A-aug [8192,3072]
__device__ __align__(256) __nv_bfloat16 g_ka[24LL << 20];    // k B-aug [8192,3072] (b-major rows)
__device__ __align__(256) __nv_bfloat16 g_va[24LL << 20];    // v^T B-aug [4][1024,6144]
__device__ float g_f32[(size_t)Bq * Sq * Eq];                // fp32 temp (v only)
__device__ float g_s[(size_t)Bq * Sq * Sq];                  // fp32 logits

// ---------------- helpers ----------------
__device__ __forceinline__ uint32_t smem_u32(const void* p) {
    uint32_t a;
    asm("{ .reg .u64 t; cvta.to.shared.u64 t, %1; cvt.u32.u64 %0, t; }" : "=r"(a) : "l"(p));
    return a;
}
__device__ __forceinline__ void cpasync16(uint32_t dst, const void* src) {
    asm volatile("cp.async.cg.shared.global [%0], [%1], 16;" :: "r"(dst), "l"(src));
}
__device__ __forceinline__ void split2(float v, __nv_bfloat16& h, __nv_bfloat16& l) {
    h = __float2bfloat16(v);
    l = __float2bfloat16(v - __bfloat162float(h));
}
__device__ __forceinline__ void mma16816(float* d, const uint32_t* a, const uint32_t* b) {
    asm volatile(
        "mma.sync.aligned.m16n8k16.row.col.f32.bf16.bf16.f32 "
        "{%0,%1,%2,%3}, {%4,%5,%6,%7}, {%8,%9}, {%0,%1,%2,%3};"
        : "+f"(d[0]), "+f"(d[1]), "+f"(d[2]), "+f"(d[3])
        : "r"(a[0]), "r"(a[1]), "r"(a[2]), "r"(a[3]), "r"(b[0]), "r"(b[1]));
}
__device__ __forceinline__ void ldsm4(uint32_t* r, uint32_t a) {
    asm volatile("ldmatrix.sync.aligned.m8n8.x4.shared.b16 {%0,%1,%2,%3}, [%4];"
                 : "=r"(r[0]), "=r"(r[1]), "=r"(r[2]), "=r"(r[3]) : "r"(a));
}

// ---------------- split fp32 -> augmented bf16 (row-major [R, 3K]) ----------------
template <bool APAT, bool TRANS>
__global__ __launch_bounds__(256) void split_aug(const float* __restrict__ src,
                                                 __nv_bfloat16* __restrict__ dst,
                                                 int Rout, int K, long long sZ, long long dZ) {
    src += blockIdx.y * sZ;
    dst += blockIdx.y * dZ;
    long long idx = (long long)blockIdx.x * 256 + threadIdx.x;
    int row, kp;
    float v0, v1;
    if (TRANS) {
        row = (int)(idx % Rout);
        kp = (int)(idx / Rout) * 2;
        v0 = src[(long long)kp * Rout + row];
        v1 = src[(long long)(kp + 1) * Rout + row];
    } else {
        const int hk = K >> 1;
        row = (int)(idx / hk);
        kp = (int)(idx % hk) * 2;
        v0 = src[(long long)row * K + kp];
        v1 = src[(long long)row * K + kp + 1];
    }
    __nv_bfloat16 h0, l0, h1, l1;
    split2(v0, h0, l0);
    split2(v1, h1, l1);
    __nv_bfloat162 H, L;
    H.x = h0; H.y = h1;
    L.x = l0; L.y = l1;
    __nv_bfloat162* d = (__nv_bfloat162*)(dst + (long long)row * 3 * K);
    d[kp >> 1] = H;
    d[(K + kp) >> 1] = APAT ? H : L;
    d[(2 * K + kp) >> 1] = APAT ? L : H;
}

// ---------------- pipelined bf16 mma.sync GEMM, CTA 128x256, warp 64x64 ----------------
// EPI: 0 = f32 C; 1 = A-aug bf16 (hi,hi,lo) at aux[row*3072 + {n,1024+n,2048+n}]; 2 = B-aug (hi,lo,hi)
template <int EPI>
__global__ __launch_bounds__(256, 1)
void gemm_bf16(const __nv_bfloat16* __restrict__ A, const __nv_bfloat16* __restrict__ B,
               float* __restrict__ Cf, __nv_bfloat16* __restrict__ aux,
               int N, int Kp, long long aZ, long long bZ, long long cZ) {
    extern __shared__ char smem[];
    const uint32_t sb = smem_u32(smem);
    const int tid = threadIdx.x;
    const int lane = tid & 31, g = lane >> 2, c = lane & 3;
    const int wid = tid >> 5, wm = wid & 1, wn = wid >> 1;   // 2 x 4 warps
    const int KT = Kp >> 6;

    const char* Ab = (const char*)(A + blockIdx.z * aZ + (long long)(blockIdx.y * 128) * Kp);
    const char* Bb = (const char*)(B + blockIdx.z * bZ + (long long)(blockIdx.x * 256) * Kp);
    const long long rowbytes = (long long)Kp * 2;

    // ldmatrix per-lane offsets (within a stage)
    uint32_t aOff[4], bOff[4];
#pragma unroll
    for (int i = 0; i < 4; i++)
        aOff[i] = (wm * 64 + i * 16 + (lane & 7) + 8 * ((lane >> 3) & 1)) * ROWB + 16 * ((lane >> 4) & 1);
#pragma unroll
    for (int jp = 0; jp < 4; jp++)
        bOff[jp] = (128 + wn * 64 + jp * 16 + (lane & 7) + 8 * ((lane >> 4) & 1)) * ROWB + 16 * ((lane >> 3) & 1);

#define LOADSTAGE(s, ck)                                                                     \
    {                                                                                        \
        uint32_t d0_ = sb + (s) * STAGE_B;                                                   \
        long long off_ = (long long)(ck) * 128;                                              \
        _Pragma("unroll") for (int t = 0; t < 4; t++) {                                      \
            int idx = tid + 256 * t, r = idx >> 3, sg = (idx & 7) * 16;                      \
            cpasync16(d0_ + r * ROWB + sg, Ab + r * rowbytes + off_ + sg);                   \
        }                                                                                    \
        _Pragma("unroll") for (int t = 4; t < 12; t++) {                                     \
            int idx = tid + 256 * t, r = idx >> 3, sg = (idx & 7) * 16;                      \
            cpasync16(d0_ + r * ROWB + sg, Bb + (r - 128) * rowbytes + off_ + sg);           \
        }                                                                                    \
        asm volatile("cp.async.commit_group;");                                              \
    }

    float acc[4][8][4];
#pragma unroll
    for (int i = 0; i < 4; i++)
#pragma unroll
        for (int j = 0; j < 8; j++)
#pragma unroll
            for (int r = 0; r < 4; r++) acc[i][j][r] = 0.0f;

    LOADSTAGE(0, 0)
    LOADSTAGE(1, 1)
    LOADSTAGE(2, 2)

    for (int k = 0; k < KT; k++) {
        asm volatile("cp.async.wait_group 2;");
        __syncthreads();
        const uint32_t sk = sb + (k & 3) * STAGE_B;
#pragma unroll
        for (int ks = 0; ks < 4; ks++) {
            uint32_t af[4][4], bfr[8][2];
#pragma unroll
            for (int i = 0; i < 4; i++) ldsm4(af[i], sk + aOff[i] + ks * 32);
#pragma unroll
            for (int jp = 0; jp < 4; jp++) {
                uint32_t q[4];
                ldsm4(q, sk + bOff[jp] + ks * 32);
                bfr[2 * jp][0] = q[0];
                bfr[2 * jp][1] = q[1];
                bfr[2 * jp + 1][0] = q[2];
                bfr[2 * jp + 1][1] = q[3];
            }
#pragma unroll
            for (int i = 0; i < 4; i++)
#pragma unroll
                for (int j = 0; j < 8; j++) mma16816(acc[i][j], af[i], bfr[j]);
        }
        __syncthreads();
        if (k + 3 < KT) LOADSTAGE((k + 3) & 3, k + 3)
    }
#undef LOADSTAGE

#pragma unroll
    for (int i = 0; i < 4; i++) {
#pragma unroll
        for (int j = 0; j < 8; j++) {
            const int r0 = blockIdx.y * 128 + wm * 64 + i * 16 + g;
            const int n0 = blockIdx.x * 256 + wn * 64 + j * 8 + 2 * c;
            if (EPI == 0) {
                float* Cb = Cf + blockIdx.z * cZ;
                float2 lo, hi;
                lo.x = acc[i][j][0]; lo.y = acc[i][j][1];
                hi.x = acc[i][j][2]; hi.y = acc[i][j][3];
                *(float2*)&Cb[(long long)r0 * N + n0] = lo;
                *(float2*)&Cb[(long long)(r0 + 8) * N + n0] = hi;
            } else {
#pragma unroll
                for (int rr = 0; rr < 2; rr++) {
                    const int row = r0 + 8 * rr;
                    __nv_bfloat16 h0, l0, h1, l1;
                    split2(acc[i][j][2 * rr], h0, l0);
                    split2(acc[i][j][2 * rr + 1], h1, l1);
                    __nv_bfloat162 H, L;
                    H.x = h0; H.y = h1;
                    L.x = l0; L.y = l1;
                    __nv_bfloat162* p2 = (__nv_bfloat162*)(aux + (long long)row * 3072);
                    p2[n0 >> 1] = H;
                    p2[(1024 + n0) >> 1] = (EPI == 1) ? H : L;
                    p2[(2048 + n0) >> 1] = (EPI == 1) ? L : H;
                }
            }
        }
    }
}

// ---------------- softmax + /32, writing P A-aug [row, 6144] directly ----------------
__global__ __launch_bounds__(256) void softmax_aug(const float* __restrict__ S,
                                                   __nv_bfloat16* __restrict__ pa) {
    const float* row = S + (long long)blockIdx.x * Sq;
    __nv_bfloat16* d = pa + (long long)blockIdx.x * 6144;
    const int tid = threadIdx.x;
    float vals[8], m = -INFINITY;
#pragma unroll
    for (int i = 0; i < 8; i++) { vals[i] = row[tid + i * 256]; m = fmaxf(m, vals[i]); }
    __shared__ float red[256];
    red[tid] = m;
    __syncthreads();
    for (int s = 128; s > 0; s >>= 1) { if (tid < s) red[tid] = fmaxf(red[tid], red[tid + s]); __syncthreads(); }
    m = red[0];
    __syncthreads();
    float sum = 0.f;
#pragma unroll
    for (int i = 0; i < 8; i++) { vals[i] = expf(vals[i] - m); sum += vals[i]; }
    red[tid] = sum;
    __syncthreads();
    for (int s = 128; s > 0; s >>= 1) { if (tid < s) red[tid] += red[tid + s]; __syncthreads(); }
    const float inv = 1.0f / (red[0] * 32.0f);
#pragma unroll
    for (int i = 0; i < 8; i++) {
        const int j = tid + i * 256;
        __nv_bfloat16 h, l;
        split2(vals[i] * inv, h, l);
        d[j] = h;
        d[2048 + j] = h;
        d[4096 + j] = l;
    }
}

extern "C" void kernel_launch(void* const* d_in, const int* in_sizes, int n_in,
                              void* d_out, int out_size) {
    const float* values  = (const float*)d_in[0];
    const float* keys    = (const float*)d_in[1];
    const float* queries = (const float*)d_in[2];
    const float* Wv = (const float*)d_in[3];
    const float* Wk = (const float*)d_in[4];
    const float* Wq = (const float*)d_in[5];
    float* out = (float*)d_out;

    __nv_bfloat16 *big, *wb, *qa, *ka, *va;
    float *f32, *sc;
    cudaGetSymbolAddress((void**)&big, g_big);
    cudaGetSymbolAddress((void**)&wb, g_wb);
    cudaGetSymbolAddress((void**)&qa, g_qa);
    cudaGetSymbolAddress((void**)&ka, g_ka);
    cudaGetSymbolAddress((void**)&va, g_va);
    cudaGetSymbolAddress((void**)&f32, g_f32);
    cudaGetSymbolAddress((void**)&sc, g_s);

    cudaFuncSetAttribute(gemm_bf16<0>, cudaFuncAttributeMaxDynamicSharedMemorySize, SMEM_T);
    cudaFuncSetAttribute(gemm_bf16<1>, cudaFuncAttributeMaxDynamicSharedMemorySize, SMEM_T);
    cudaFuncSetAttribute(gemm_bf16<2>, cudaFuncAttributeMaxDynamicSharedMemorySize, SMEM_T);

    const struct { const float* X; const float* W; } P3[3] = {{queries, Wq}, {keys, Wk}, {values, Wv}};

    for (int p = 0; p < 3; p++) {
        split_aug<true, false><<<dim3(16384, 1), 256>>>(P3[p].X, big, 8192, 1024, 0, 0);
        split_aug<false, true><<<dim3(2048, 1), 256>>>(P3[p].W, wb, 1024, 1024, 0, 0);
        if (p == 0)
            gemm_bf16<1><<<dim3(4, 64, 1), 256, SMEM_T>>>(big, wb, nullptr, qa, 1024, 3072, 0, 0, 0);
        else if (p == 1)
            gemm_bf16<2><<<dim3(4, 64, 1), 256, SMEM_T>>>(big, wb, nullptr, ka, 1024, 3072, 0, 0, 0);
        else {
            gemm_bf16<0><<<dim3(4, 64, 1), 256, SMEM_T>>>(big, wb, f32, nullptr, 1024, 3072, 0, 0, 0);
            split_aug<false, true><<<dim3(4096, 4), 256>>>(f32, va, 1024, 2048,
                                                           (long long)Sq * Eq, 1024LL * 6144);
        }
    }

    // scores = q @ k^T per batch
    gemm_bf16<0><<<dim3(8, 16, 4), 256, SMEM_T>>>(qa, ka, sc, nullptr, 2048, 3072,
                                                  2048LL * 3072, 2048LL * 3072, (long long)Sq * Sq);
    // softmax + /32 -> P A-aug
    softmax_aug<<<Bq * Sq, 256>>>(sc, big);
    // out = P @ v per batch
    gemm_bf16<0><<<dim3(4, 16, 4), 256, SMEM_T>>>(big, va, out, nullptr, 1024, 6144,
                                                  2048LL * 6144, 1024LL * 6144, (long long)Sq * Eq);

    (void)in_sizes; (void)n_in; (void)out_size;
}